// round 11
// baseline (speedup 1.0000x reference)
#include <cuda_runtime.h>
#include <cuda_fp16.h>
#include <cstdint>

#define H64 64
#define EE_MAX 50000
#define NN_MAX 20000

// ---------------- scratch (static device globals) ---------------------------
__device__ __half   g_ht0[EE_MAX * H64 + 256];  // edge MLP out, fp16, [j][e]
__device__ __half   g_ht1[EE_MAX * H64 + 256];
__device__ uint32_t g_w2bh0[33 * 2176];         // fp16x2 packed B chunk64s, L0
__device__ uint32_t g_w2bh1[66 * 2176];         // fp16x2 packed B chunk64s, L1
__device__ float    g_agg0[NN_MAX * H64];
__device__ float    g_agg1[NN_MAX * H64];

// ---------------- PTX helpers ------------------------------------------------
__device__ __forceinline__ uint32_t smem_u32(const void* p) {
    return (uint32_t)__cvta_generic_to_shared(p);
}
__device__ __forceinline__ void cp_async16(uint32_t s, const void* g) {
    asm volatile("cp.async.cg.shared.global [%0], [%1], 16;" :: "r"(s), "l"(g));
}
#define CP_COMMIT() asm volatile("cp.async.commit_group;" ::: "memory")
#define CP_WAIT1()  asm volatile("cp.async.wait_group 1;" ::: "memory")
#define GDC_WAIT()  asm volatile("griddepcontrol.wait;" ::: "memory")

__device__ __forceinline__ uint32_t packf16(float v0, float v1) {
    uint32_t d;
    asm("cvt.rn.f16x2.f32 %0, %1, %2;" : "=r"(d) : "f"(v1), "f"(v0));
    return d;
}

// fp16-accumulator MMA: d(c) are 2 x b32 regs holding 4 fp16 values
__device__ __forceinline__ void mma_f16acc(uint32_t* d, uint32_t a0, uint32_t a1,
                                           uint32_t a2, uint32_t a3,
                                           uint32_t b0, uint32_t b1) {
    asm volatile(
        "mma.sync.aligned.m16n8k16.row.col.f16.f16.f16.f16 "
        "{%0,%1}, {%2,%3,%4,%5}, {%6,%7}, {%0,%1};"
        : "+r"(d[0]), "+r"(d[1])
        : "r"(a0), "r"(a1), "r"(a2), "r"(a3), "r"(b0), "r"(b1));
}

// ---------------- kernel A: setup mega-kernel -------------------------------
__global__ void __launch_bounds__(256)
setup_kernel(const float* __restrict__ ea,
             const float* __restrict__ w1_0, const float* __restrict__ b1_0,
             const float* __restrict__ w1_1, const float* __restrict__ b1_1,
             const float* __restrict__ w2_0, const float* __restrict__ b2_0,
             const float* __restrict__ w2_1, const float* __restrict__ b2_1,
             const float* __restrict__ x,
             const float* __restrict__ root_0, const float* __restrict__ bias_0,
             int E, int N, int ebpj, int nb_mlp, int nb_prep)
{
    int b = blockIdx.x, tid = threadIdx.x;

    if (b < nb_mlp) {
        // ---- edge MLP (both layers per thread) ----
        int j = b / ebpj, eb = b % ebpj;
        int e = eb * 256 + tid;
        if (e >= E) return;
        float a0 = __ldg(&ea[2 * e]);
        float a1 = __ldg(&ea[2 * e + 1]);
        float v0 = fmaf(a0, __ldg(&w1_0[j]), fmaf(a1, __ldg(&w1_0[H64 + j]), __ldg(&b1_0[j])));
        float v1 = fmaf(a0, __ldg(&w1_1[j]), fmaf(a1, __ldg(&w1_1[H64 + j]), __ldg(&b1_1[j])));
        g_ht0[(size_t)j * E + e] = __float2half(fmaxf(v0, 0.0f));
        g_ht1[(size_t)j * E + e] = __float2half(fmaxf(v1, 0.0f));
        return;
    }
    if (b < nb_mlp + nb_prep) {
        // ---- pack B chunk64 tables (pair layout) ----
        int idx = (b - nb_mlp) * 256 + tid;          // < 66*2048
        int c = idx >> 11, rem = idx & 2047;
        int row = rem >> 7;
        int n   = (rem >> 1) & 63;
        int p   = rem & 1;
        int s = row >> 2, t = row & 3;
        int k0 = 2 * t + 8 * p;
        int word = row * 136 + n * 2 + p;

        if (c < 33) {       // layer 0
            float v0 = 0.f, v1 = 0.f;
            if (c < 32) {
                int k = 2 * c + (s >> 1);
                int i = (s & 1) * 16 + k0;
                v0 = w2_0[k * 2048 + i * H64 + n];
                v1 = w2_0[k * 2048 + (i + 1) * H64 + n];
            } else if (s < 2) {
                int i = s * 16 + k0;
                v0 = b2_0[i * H64 + n];
                v1 = b2_0[(i + 1) * H64 + n];
            }
            g_w2bh0[c * 2176 + word] = packf16(v0, v1);
        }
        {                   // layer 1
            int ih = (c >= 33) ? 1 : 0;
            int cc = c - 33 * ih;
            float v0 = 0.f, v1 = 0.f;
            if (cc < 32) {
                int k = 2 * cc + (s >> 1);
                int i = ih * 32 + (s & 1) * 16 + k0;
                v0 = w2_1[k * 4096 + i * H64 + n];
                v1 = w2_1[k * 4096 + (i + 1) * H64 + n];
            } else if (s < 2) {
                int i = ih * 32 + s * 16 + k0;
                v0 = b2_1[i * H64 + n];
                v1 = b2_1[(i + 1) * H64 + n];
            }
            g_w2bh1[c * 2176 + word] = packf16(v0, v1);
        }
        return;
    }
    // ---- root0: agg0 = x @ root_0 + bias_0 ; agg1 = 0 ----
    int idx = (b - nb_mlp - nb_prep) * 256 + tid;
    if (idx >= N * H64) return;
    int n = idx >> 6, t = idx & 63;
    float v = __ldg(&bias_0[t]);
    const float* xr = x + (size_t)n * 32;
    #pragma unroll
    for (int i = 0; i < 32; i++)
        v = fmaf(__ldg(&xr[i]), __ldg(&root_0[i * H64 + t]), v);
    g_agg0[idx] = v;
    g_agg1[idx] = 0.0f;
}

// ---------------- fused msg GEMM (fp16-acc mma) + scatter [+ root backfill]
// blocks [0, gridFuse): CTA = 128 edges x 64 outs, 4 warps (32x64 warp tile),
//   K-chunks of 64, triple-buffered cp.async for B + h(fp16).
//   fp16 accumulation within a chunk; promoted to fp32 regs every chunk.
// blocks >= gridFuse (layer 1 only): root1 term, grid-stride atomicAdd.
template<int IN_C, bool RELU_IN>
__global__ void __launch_bounds__(128, 3)
fused_mma_kernel(const float* __restrict__ x, const int* __restrict__ ei, int E,
                 const __half* __restrict__ ht, const uint32_t* __restrict__ w2b,
                 float* __restrict__ agg,
                 const float* __restrict__ rootW, const float* __restrict__ rootB,
                 int N, int gridFuse, int rootBlocks)
{
    constexpr int NCHUNK = (IN_C == 32) ? 33 : 66;
    constexpr int XROW   = IN_C + 4;
    constexpr int B_OFF  = 0;                 // 3 x 8704
    constexpr int H_OFF  = 26112;             // 3 x 512 ([slot][kk][e], fp16)
    constexpr int X_OFF  = 27648;
    constexpr int DST_OFF = X_OFF + 128 * XROW * 4;

    int tid = threadIdx.x;

    if (blockIdx.x >= (unsigned)gridFuse) {
        // ---- root backfill path (layer 1 only; no smem, no syncs) ----
        GDC_WAIT();
        int stride = rootBlocks * 128;
        for (int idx = (blockIdx.x - gridFuse) * 128 + tid; idx < N * H64; idx += stride) {
            int n = idx >> 6, t = idx & 63;
            float v = __ldg(&rootB[t]);
            const float* xr = x + (size_t)n * H64;
            #pragma unroll
            for (int i = 0; i < H64; i++)
                v = fmaf(fmaxf(__ldg(&xr[i]), 0.0f), __ldg(&rootW[i * H64 + t]), v);
            atomicAdd(&agg[idx], v);
        }
        return;
    }

    extern __shared__ char smem[];
    float* x_s   = (float*)(smem + X_OFF);
    int*   dst_s = (int*)(smem + DST_OFF);
    uint32_t sbase = smem_u32(smem);

    int e0 = blockIdx.x * 128;

    // ---- prefetch: B chunk (8704 B) + 2 h columns (512 B fp16) ----
    auto prefetch = [&](int c) {
        if (c < NCHUNK) {
            int slot = c % 3;
            uint32_t bs = sbase + B_OFF + slot * 8704;
            const char* g = (const char*)w2b + (size_t)c * 8704;
            #pragma unroll
            for (int o = 0; o < 8192; o += 2048)
                cp_async16(bs + o + tid * 16, g + o + tid * 16);
            if (tid < 32) cp_async16(bs + 8192 + tid * 16, g + 8192 + tid * 16);
            bool isBias = (IN_C == 32) ? (c == 32) : (c == 32 || c == 65);
            if (!isBias && tid < 32) {
                int cc = (IN_C == 32) ? c : ((c < 33) ? c : c - 33);
                int kk = tid >> 4, ln = tid & 15;
                cp_async16(sbase + H_OFF + slot * 512 + kk * 256 + ln * 16,
                           ht + (size_t)(2 * cc + kk) * E + e0 + ln * 8);
            }
        }
        CP_COMMIT();
    };

    // ---- gather x[src] tile ----
    auto gather_x = [&]() {
        constexpr int XV = IN_C / 4;
        for (int q = tid; q < 128 * XV; q += 128) {
            int e = q / XV, cc = q % XV;
            int ge = e0 + e;
            int s = (ge < E) ? ei[ge] : 0;
            float4 v = *(const float4*)(x + (size_t)s * IN_C + cc * 4);
            if (RELU_IN) {
                v.x = fmaxf(v.x, 0.0f); v.y = fmaxf(v.y, 0.0f);
                v.z = fmaxf(v.z, 0.0f); v.w = fmaxf(v.w, 0.0f);
            }
            *(float4*)&x_s[e * XROW + cc * 4] = v;
        }
    };

    dst_s[tid] = (e0 + tid < E) ? ei[E + e0 + tid] : -1;   // reads input only

    if (RELU_IN) {
        // B/h tables were produced two kernels ago -> safe before the wait;
        // x == agg0 from the previous kernel -> gather after the wait.
        prefetch(0); prefetch(1);
        GDC_WAIT();
        gather_x();
    } else {
        // x is a harness input -> gather before the wait; tables need setup.
        gather_x();
        GDC_WAIT();
        prefetch(0); prefetch(1);
    }
    __syncthreads();   // x_s / dst_s visible

    const int w    = tid >> 5;
    const int lane = tid & 31;
    const int gid  = lane >> 2;
    const int tig  = lane & 3;

    int rows[4];
    #pragma unroll
    for (int j = 0; j < 4; j++) rows[j] = w * 32 + j * 8 + gid;

    float xreg[4][8];
    auto load_xreg = [&](int ih) {
        #pragma unroll
        for (int r = 0; r < 4; r++)
            #pragma unroll
            for (int j = 0; j < 8; j++)
                xreg[r][j] = x_s[rows[r] * XROW + ih +
                                 (j >> 2) * 16 + 2 * tig + 8 * ((j >> 1) & 1) + (j & 1)];
    };
    load_xreg(0);

    float acc[2][8][4];
    #pragma unroll
    for (int mt = 0; mt < 2; mt++)
        #pragma unroll
        for (int q = 0; q < 8; q++)
            #pragma unroll
            for (int u = 0; u < 4; u++) acc[mt][q][u] = 0.0f;

    for (int c = 0; c < NCHUNK; c++) {
        if (IN_C == 64 && c == 33) load_xreg(32);
        CP_WAIT1();
        __syncthreads();
        prefetch(c + 2);

        int slot = c % 3;
        bool isBias = (IN_C == 32) ? (c == 32) : (c == 32 || c == 65);
        float hk[2][4];
        if (isBias) {
            #pragma unroll
            for (int j = 0; j < 4; j++) { hk[0][j] = 1.0f; hk[1][j] = 1.0f; }
        } else {
            const __half* hb = (const __half*)(smem + H_OFF + slot * 512);
            #pragma unroll
            for (int j = 0; j < 4; j++) {
                hk[0][j] = __half2float(hb[rows[j]]);
                hk[1][j] = __half2float(hb[128 + rows[j]]);
            }
        }

        // fp16 accumulators for this chunk
        uint32_t acc16[2][8][2];
        #pragma unroll
        for (int mt = 0; mt < 2; mt++)
            #pragma unroll
            for (int q = 0; q < 8; q++) { acc16[mt][q][0] = 0u; acc16[mt][q][1] = 0u; }

        uint32_t bbase = sbase + B_OFF + slot * 8704;
        #pragma unroll
        for (int s = 0; s < 4; s++) {
            int kk = s >> 1, jb = (s & 1) * 4;
            uint32_t a[2][4];
            #pragma unroll
            for (int mt = 0; mt < 2; mt++) {
                float h0 = hk[kk][mt * 2], h1 = hk[kk][mt * 2 + 1];
                const float* x0 = xreg[mt * 2];
                const float* x1 = xreg[mt * 2 + 1];
                a[mt][0] = packf16(h0 * x0[jb + 0], h0 * x0[jb + 1]);
                a[mt][1] = packf16(h1 * x1[jb + 0], h1 * x1[jb + 1]);
                a[mt][2] = packf16(h0 * x0[jb + 2], h0 * x0[jb + 3]);
                a[mt][3] = packf16(h1 * x1[jb + 2], h1 * x1[jb + 3]);
            }
            uint32_t brow = bbase + (uint32_t)(s * 4 + tig) * 544 + (uint32_t)gid * 8;
            #pragma unroll
            for (int q = 0; q < 8; q++) {
                uint32_t b0, b1;
                asm volatile("ld.shared.v2.b32 {%0, %1}, [%2];"
                             : "=r"(b0), "=r"(b1) : "r"(brow + q * 64));
                mma_f16acc(acc16[0][q], a[0][0], a[0][1], a[0][2], a[0][3], b0, b1);
                mma_f16acc(acc16[1][q], a[1][0], a[1][1], a[1][2], a[1][3], b0, b1);
            }
        }

        // promote chunk partials to fp32
        #pragma unroll
        for (int mt = 0; mt < 2; mt++)
            #pragma unroll
            for (int q = 0; q < 8; q++) {
                float2 f01 = __half22float2(*(__half2*)&acc16[mt][q][0]);
                float2 f23 = __half22float2(*(__half2*)&acc16[mt][q][1]);
                acc[mt][q][0] += f01.x; acc[mt][q][1] += f01.y;
                acc[mt][q][2] += f23.x; acc[mt][q][3] += f23.y;
            }
    }

    // ---- scatter-add into agg[dst] ----
    #pragma unroll
    for (int mt = 0; mt < 2; mt++) {
        int d0 = dst_s[rows[mt * 2]];
        int d1 = dst_s[rows[mt * 2 + 1]];
        float* p0 = agg + (size_t)(d0 < 0 ? 0 : d0) * H64;
        float* p1 = agg + (size_t)(d1 < 0 ? 0 : d1) * H64;
        #pragma unroll
        for (int q = 0; q < 8; q++) {
            int n = q * 8 + tig * 2;
            if (d0 >= 0) {
                atomicAdd(p0 + n,     acc[mt][q][0]);
                atomicAdd(p0 + n + 1, acc[mt][q][1]);
            }
            if (d1 >= 0) {
                atomicAdd(p1 + n,     acc[mt][q][2]);
                atomicAdd(p1 + n + 1, acc[mt][q][3]);
            }
        }
    }
}

// ---------------- relu out (vectorized, PDL wait) ---------------------------
__global__ void __launch_bounds__(256)
relu_out_kernel(const float4* __restrict__ in, float4* __restrict__ out, int n4)
{
    GDC_WAIT();
    int stride = gridDim.x * blockDim.x;
    for (int i = blockIdx.x * blockDim.x + threadIdx.x; i < n4; i += stride) {
        float4 v = in[i];
        v.x = fmaxf(v.x, 0.0f); v.y = fmaxf(v.y, 0.0f);
        v.z = fmaxf(v.z, 0.0f); v.w = fmaxf(v.w, 0.0f);
        out[i] = v;
    }
}

// ---------------- launch -----------------------------------------------------
extern "C" void kernel_launch(void* const* d_in, const int* in_sizes, int n_in,
                              void* d_out, int out_size)
{
    const float* x      = (const float*)d_in[0];
    const int*   ei     = (const int*)  d_in[1];
    const float* ea     = (const float*)d_in[2];
    const float* w1_0   = (const float*)d_in[3];
    const float* b1_0   = (const float*)d_in[4];
    const float* w2_0   = (const float*)d_in[5];
    const float* b2_0   = (const float*)d_in[6];
    const float* root_0 = (const float*)d_in[7];
    const float* bias_0 = (const float*)d_in[8];
    const float* w1_1   = (const float*)d_in[9];
    const float* b1_1   = (const float*)d_in[10];
    const float* w2_1   = (const float*)d_in[11];
    const float* b2_1   = (const float*)d_in[12];
    const float* root_1 = (const float*)d_in[13];
    const float* bias_1 = (const float*)d_in[14];

    const int N = in_sizes[0] / 32;   // 20000
    const int E = in_sizes[1] / 2;    // 50000

    void* p;
    cudaGetSymbolAddress(&p, g_ht0);   __half* ht0 = (__half*)p;
    cudaGetSymbolAddress(&p, g_ht1);   __half* ht1 = (__half*)p;
    cudaGetSymbolAddress(&p, g_w2bh0); uint32_t* w2b0 = (uint32_t*)p;
    cudaGetSymbolAddress(&p, g_w2bh1); uint32_t* w2b1 = (uint32_t*)p;
    cudaGetSymbolAddress(&p, g_agg0);  float* agg0 = (float*)p;
    cudaGetSymbolAddress(&p, g_agg1);  float* agg1 = (float*)p;

    const int smem0 = 27648 + 128 * 36 * 4 + 512;   // 46592
    const int smem1 = 27648 + 128 * 68 * 4 + 512;   // 62976
    cudaFuncSetAttribute(fused_mma_kernel<32, false>,
                         cudaFuncAttributeMaxDynamicSharedMemorySize, smem0);
    cudaFuncSetAttribute(fused_mma_kernel<64, true>,
                         cudaFuncAttributeMaxDynamicSharedMemorySize, smem1);

    // ---- launch A: setup mega-kernel (plain launch) ----
    const int ebpj    = (E + 255) / 256;
    const int nb_mlp  = ebpj * H64;
    const int nb_prep = (66 * 2048) / 256;          // 528
    const int nb_root = (N * H64 + 255) / 256;
    setup_kernel<<<nb_mlp + nb_prep + nb_root, 256>>>(
        ea, w1_0, b1_0, w1_1, b1_1, w2_0, b2_0, w2_1, b2_1,
        x, root_0, bias_0, E, N, ebpj, nb_mlp, nb_prep);

    const int grid_fuse = (E + 127) / 128;
    const int ROOT_BLKS = 592;

    cudaLaunchAttribute pdl[1];
    pdl[0].id = cudaLaunchAttributeProgrammaticStreamSerialization;
    pdl[0].val.programmaticStreamSerializationAllowed = 1;

    // ---- launch B: fused layer 0 (PDL after setup) ----
    {
        cudaLaunchConfig_t cfg{};
        cfg.gridDim = dim3(grid_fuse);
        cfg.blockDim = dim3(128);
        cfg.dynamicSmemBytes = smem0;
        cfg.stream = 0;
        cfg.attrs = pdl;
        cfg.numAttrs = 1;
        const float* nW = nullptr; const float* nB = nullptr;
        cudaLaunchKernelEx(&cfg, fused_mma_kernel<32, false>,
                           x, ei, E, (const __half*)ht0, (const uint32_t*)w2b0,
                           agg0, nW, nB, N, grid_fuse, 0);
    }

    // ---- launch C: fused layer 1 + root1 backfill (PDL after B) ----
    {
        cudaLaunchConfig_t cfg{};
        cfg.gridDim = dim3(grid_fuse + ROOT_BLKS);
        cfg.blockDim = dim3(128);
        cfg.dynamicSmemBytes = smem1;
        cfg.stream = 0;
        cfg.attrs = pdl;
        cfg.numAttrs = 1;
        cudaLaunchKernelEx(&cfg, fused_mma_kernel<64, true>,
                           (const float*)agg0, ei, E, (const __half*)ht1,
                           (const uint32_t*)w2b1, agg1,
                           root_1, bias_1, N, grid_fuse, ROOT_BLKS);
    }

    // ---- launch D: relu out (PDL after C) ----
    {
        cudaLaunchConfig_t cfg{};
        cfg.gridDim = dim3(640);
        cfg.blockDim = dim3(256);
        cfg.dynamicSmemBytes = 0;
        cfg.stream = 0;
        cfg.attrs = pdl;
        cfg.numAttrs = 1;
        cudaLaunchKernelEx(&cfg, relu_out_kernel,
                           (const float4*)agg1, (float4*)d_out, (N * H64) / 4);
    }
}

// round 12
// speedup vs baseline: 1.1205x; 1.1205x over previous
#include <cuda_runtime.h>
#include <cuda_fp16.h>
#include <cstdint>

#define H64 64
#define EE_MAX 50000
#define NN_MAX 20000

// ---------------- scratch (static device globals) ---------------------------
__device__ __half   g_ht0[EE_MAX * H64 + 256];  // edge MLP out, fp16, [j][e]
__device__ __half   g_ht1[EE_MAX * H64 + 256];
__device__ uint32_t g_w2bh0[33 * 2176];         // fp16x2 packed B chunk64s, L0
__device__ uint32_t g_w2bh1[66 * 2176];         // fp16x2 packed B chunk64s, L1
__device__ float    g_agg0[NN_MAX * H64];
__device__ float    g_agg1[NN_MAX * H64];

// ---------------- PTX helpers ------------------------------------------------
__device__ __forceinline__ uint32_t smem_u32(const void* p) {
    return (uint32_t)__cvta_generic_to_shared(p);
}
__device__ __forceinline__ void cp_async16(uint32_t s, const void* g) {
    asm volatile("cp.async.cg.shared.global [%0], [%1], 16;" :: "r"(s), "l"(g));
}
#define CP_COMMIT() asm volatile("cp.async.commit_group;" ::: "memory")
#define CP_WAIT1()  asm volatile("cp.async.wait_group 1;" ::: "memory")
#define GDC_WAIT()  asm volatile("griddepcontrol.wait;" ::: "memory")

__device__ __forceinline__ uint32_t packf16(float v0, float v1) {
    uint32_t d;
    asm("cvt.rn.f16x2.f32 %0, %1, %2;" : "=r"(d) : "f"(v1), "f"(v0));
    return d;
}

// fp32-accumulator fp16 MMA (proven fastest path on sm_103 legacy tensor)
__device__ __forceinline__ void mma_f16(float* d, uint32_t a0, uint32_t a1,
                                        uint32_t a2, uint32_t a3,
                                        uint32_t b0, uint32_t b1) {
    asm volatile(
        "mma.sync.aligned.m16n8k16.row.col.f32.f16.f16.f32 "
        "{%0,%1,%2,%3}, {%4,%5,%6,%7}, {%8,%9}, {%0,%1,%2,%3};"
        : "+f"(d[0]), "+f"(d[1]), "+f"(d[2]), "+f"(d[3])
        : "r"(a0), "r"(a1), "r"(a2), "r"(a3), "r"(b0), "r"(b1));
}

// ---------------- kernel A: setup mega-kernel -------------------------------
__global__ void __launch_bounds__(256)
setup_kernel(const float* __restrict__ ea,
             const float* __restrict__ w1_0, const float* __restrict__ b1_0,
             const float* __restrict__ w1_1, const float* __restrict__ b1_1,
             const float* __restrict__ w2_0, const float* __restrict__ b2_0,
             const float* __restrict__ w2_1, const float* __restrict__ b2_1,
             const float* __restrict__ x,
             const float* __restrict__ root_0, const float* __restrict__ bias_0,
             int E, int N, int ebpj, int nb_mlp, int nb_prep)
{
    int b = blockIdx.x, tid = threadIdx.x;

    if (b < nb_mlp) {
        // ---- edge MLP (both layers per thread) ----
        int j = b / ebpj, eb = b % ebpj;
        int e = eb * 256 + tid;
        if (e >= E) return;
        float a0 = __ldg(&ea[2 * e]);
        float a1 = __ldg(&ea[2 * e + 1]);
        float v0 = fmaf(a0, __ldg(&w1_0[j]), fmaf(a1, __ldg(&w1_0[H64 + j]), __ldg(&b1_0[j])));
        float v1 = fmaf(a0, __ldg(&w1_1[j]), fmaf(a1, __ldg(&w1_1[H64 + j]), __ldg(&b1_1[j])));
        g_ht0[(size_t)j * E + e] = __float2half(fmaxf(v0, 0.0f));
        g_ht1[(size_t)j * E + e] = __float2half(fmaxf(v1, 0.0f));
        return;
    }
    if (b < nb_mlp + nb_prep) {
        // ---- pack B chunk64 tables (pair layout) ----
        int idx = (b - nb_mlp) * 256 + tid;          // < 66*2048
        int c = idx >> 11, rem = idx & 2047;
        int row = rem >> 7;
        int n   = (rem >> 1) & 63;
        int p   = rem & 1;
        int s = row >> 2, t = row & 3;
        int k0 = 2 * t + 8 * p;
        int word = row * 136 + n * 2 + p;

        if (c < 33) {       // layer 0
            float v0 = 0.f, v1 = 0.f;
            if (c < 32) {
                int k = 2 * c + (s >> 1);
                int i = (s & 1) * 16 + k0;
                v0 = w2_0[k * 2048 + i * H64 + n];
                v1 = w2_0[k * 2048 + (i + 1) * H64 + n];
            } else if (s < 2) {
                int i = s * 16 + k0;
                v0 = b2_0[i * H64 + n];
                v1 = b2_0[(i + 1) * H64 + n];
            }
            g_w2bh0[c * 2176 + word] = packf16(v0, v1);
        }
        {                   // layer 1
            int ih = (c >= 33) ? 1 : 0;
            int cc = c - 33 * ih;
            float v0 = 0.f, v1 = 0.f;
            if (cc < 32) {
                int k = 2 * cc + (s >> 1);
                int i = ih * 32 + (s & 1) * 16 + k0;
                v0 = w2_1[k * 4096 + i * H64 + n];
                v1 = w2_1[k * 4096 + (i + 1) * H64 + n];
            } else if (s < 2) {
                int i = ih * 32 + s * 16 + k0;
                v0 = b2_1[i * H64 + n];
                v1 = b2_1[(i + 1) * H64 + n];
            }
            g_w2bh1[c * 2176 + word] = packf16(v0, v1);
        }
        return;
    }
    // ---- root0: agg0 = x @ root_0 + bias_0 ; agg1 = 0 ----
    int idx = (b - nb_mlp - nb_prep) * 256 + tid;
    if (idx >= N * H64) return;
    int n = idx >> 6, t = idx & 63;
    float v = __ldg(&bias_0[t]);
    const float* xr = x + (size_t)n * 32;
    #pragma unroll
    for (int i = 0; i < 32; i++)
        v = fmaf(__ldg(&xr[i]), __ldg(&root_0[i * H64 + t]), v);
    g_agg0[idx] = v;
    g_agg1[idx] = 0.0f;
}

// ---------------- fused msg GEMM (mma.sync fp16->fp32) + scatter [+ root] ---
// blocks [0, gridFuse): CTA = 128 edges x 64 outs, 4 warps (32x64 warp tile),
//   K-chunks of 64, triple-buffered cp.async for B + h(fp16).
// blocks >= gridFuse (layer 1 only): root1 term, grid-stride atomicAdd.
// PDL ordering: layer 1 prefetches B/h (written 2 kernels ago) BEFORE the
//   wait, gathers x (= agg0 from previous kernel) after; layer 0 inverse.
template<int IN_C, bool RELU_IN>
__global__ void __launch_bounds__(128, 3)
fused_mma_kernel(const float* __restrict__ x, const int* __restrict__ ei, int E,
                 const __half* __restrict__ ht, const uint32_t* __restrict__ w2b,
                 float* __restrict__ agg,
                 const float* __restrict__ rootW, const float* __restrict__ rootB,
                 int N, int gridFuse, int rootBlocks)
{
    constexpr int NCHUNK = (IN_C == 32) ? 33 : 66;
    constexpr int XROW   = IN_C + 4;
    constexpr int B_OFF  = 0;                 // 3 x 8704
    constexpr int H_OFF  = 26112;             // 3 x 512 ([slot][kk][e], fp16)
    constexpr int X_OFF  = 27648;
    constexpr int DST_OFF = X_OFF + 128 * XROW * 4;

    int tid = threadIdx.x;

    if (blockIdx.x >= (unsigned)gridFuse) {
        // ---- root backfill path (layer 1 only; no smem, no syncs) ----
        GDC_WAIT();
        int stride = rootBlocks * 128;
        for (int idx = (blockIdx.x - gridFuse) * 128 + tid; idx < N * H64; idx += stride) {
            int n = idx >> 6, t = idx & 63;
            float v = __ldg(&rootB[t]);
            const float* xr = x + (size_t)n * H64;
            #pragma unroll
            for (int i = 0; i < H64; i++)
                v = fmaf(fmaxf(__ldg(&xr[i]), 0.0f), __ldg(&rootW[i * H64 + t]), v);
            atomicAdd(&agg[idx], v);
        }
        return;
    }

    extern __shared__ char smem[];
    float* x_s   = (float*)(smem + X_OFF);
    int*   dst_s = (int*)(smem + DST_OFF);
    uint32_t sbase = smem_u32(smem);

    int e0 = blockIdx.x * 128;

    // ---- prefetch: B chunk (8704 B) + 2 h columns (512 B fp16) ----
    auto prefetch = [&](int c) {
        if (c < NCHUNK) {
            int slot = c % 3;
            uint32_t bs = sbase + B_OFF + slot * 8704;
            const char* g = (const char*)w2b + (size_t)c * 8704;
            #pragma unroll
            for (int o = 0; o < 8192; o += 2048)
                cp_async16(bs + o + tid * 16, g + o + tid * 16);
            if (tid < 32) cp_async16(bs + 8192 + tid * 16, g + 8192 + tid * 16);
            bool isBias = (IN_C == 32) ? (c == 32) : (c == 32 || c == 65);
            if (!isBias && tid < 32) {
                int cc = (IN_C == 32) ? c : ((c < 33) ? c : c - 33);
                int kk = tid >> 4, ln = tid & 15;
                cp_async16(sbase + H_OFF + slot * 512 + kk * 256 + ln * 16,
                           ht + (size_t)(2 * cc + kk) * E + e0 + ln * 8);
            }
        }
        CP_COMMIT();
    };

    // ---- gather x[src] tile (relu on read for layer 1) ----
    auto gather_x = [&]() {
        constexpr int XV = IN_C / 4;
        for (int q = tid; q < 128 * XV; q += 128) {
            int e = q / XV, cc = q % XV;
            int ge = e0 + e;
            int s = (ge < E) ? ei[ge] : 0;
            float4 v = *(const float4*)(x + (size_t)s * IN_C + cc * 4);
            if (RELU_IN) {
                v.x = fmaxf(v.x, 0.0f); v.y = fmaxf(v.y, 0.0f);
                v.z = fmaxf(v.z, 0.0f); v.w = fmaxf(v.w, 0.0f);
            }
            *(float4*)&x_s[e * XROW + cc * 4] = v;
        }
    };

    dst_s[tid] = (e0 + tid < E) ? ei[E + e0 + tid] : -1;   // reads input only

    if (RELU_IN) {
        // B/h tables written two kernels ago -> prefetch before the wait;
        // x == agg0 from the previous kernel -> gather after the wait.
        prefetch(0); prefetch(1);
        GDC_WAIT();
        gather_x();
    } else {
        // x is a harness input -> gather before the wait; tables need setup.
        gather_x();
        GDC_WAIT();
        prefetch(0); prefetch(1);
    }
    __syncthreads();   // x_s / dst_s visible

    const int w    = tid >> 5;
    const int lane = tid & 31;
    const int gid  = lane >> 2;
    const int tig  = lane & 3;

    int rows[4];
    #pragma unroll
    for (int j = 0; j < 4; j++) rows[j] = w * 32 + j * 8 + gid;

    float xreg[4][8];
    auto load_xreg = [&](int ih) {
        #pragma unroll
        for (int r = 0; r < 4; r++)
            #pragma unroll
            for (int j = 0; j < 8; j++)
                xreg[r][j] = x_s[rows[r] * XROW + ih +
                                 (j >> 2) * 16 + 2 * tig + 8 * ((j >> 1) & 1) + (j & 1)];
    };
    load_xreg(0);

    float acc[2][8][4];
    #pragma unroll
    for (int mt = 0; mt < 2; mt++)
        #pragma unroll
        for (int q = 0; q < 8; q++)
            #pragma unroll
            for (int u = 0; u < 4; u++) acc[mt][q][u] = 0.0f;

    for (int c = 0; c < NCHUNK; c++) {
        if (IN_C == 64 && c == 33) load_xreg(32);
        CP_WAIT1();
        __syncthreads();
        prefetch(c + 2);

        int slot = c % 3;
        bool isBias = (IN_C == 32) ? (c == 32) : (c == 32 || c == 65);
        float hk[2][4];
        if (isBias) {
            #pragma unroll
            for (int j = 0; j < 4; j++) { hk[0][j] = 1.0f; hk[1][j] = 1.0f; }
        } else {
            const __half* hb = (const __half*)(smem + H_OFF + slot * 512);
            #pragma unroll
            for (int j = 0; j < 4; j++) {
                hk[0][j] = __half2float(hb[rows[j]]);
                hk[1][j] = __half2float(hb[128 + rows[j]]);
            }
        }

        uint32_t bbase = sbase + B_OFF + slot * 8704;
        #pragma unroll
        for (int s = 0; s < 4; s++) {
            int kk = s >> 1, jb = (s & 1) * 4;
            uint32_t a[2][4];
            #pragma unroll
            for (int mt = 0; mt < 2; mt++) {
                float h0 = hk[kk][mt * 2], h1 = hk[kk][mt * 2 + 1];
                const float* x0 = xreg[mt * 2];
                const float* x1 = xreg[mt * 2 + 1];
                a[mt][0] = packf16(h0 * x0[jb + 0], h0 * x0[jb + 1]);
                a[mt][1] = packf16(h1 * x1[jb + 0], h1 * x1[jb + 1]);
                a[mt][2] = packf16(h0 * x0[jb + 2], h0 * x0[jb + 3]);
                a[mt][3] = packf16(h1 * x1[jb + 2], h1 * x1[jb + 3]);
            }
            uint32_t brow = bbase + (uint32_t)(s * 4 + tig) * 544 + (uint32_t)gid * 8;
            #pragma unroll
            for (int q = 0; q < 8; q++) {
                uint32_t b0, b1;
                asm volatile("ld.shared.v2.b32 {%0, %1}, [%2];"
                             : "=r"(b0), "=r"(b1) : "r"(brow + q * 64));
                mma_f16(acc[0][q], a[0][0], a[0][1], a[0][2], a[0][3], b0, b1);
                mma_f16(acc[1][q], a[1][0], a[1][1], a[1][2], a[1][3], b0, b1);
            }
        }
    }

    // ---- scatter-add into agg[dst] ----
    #pragma unroll
    for (int mt = 0; mt < 2; mt++) {
        int d0 = dst_s[rows[mt * 2]];
        int d1 = dst_s[rows[mt * 2 + 1]];
        float* p0 = agg + (size_t)(d0 < 0 ? 0 : d0) * H64;
        float* p1 = agg + (size_t)(d1 < 0 ? 0 : d1) * H64;
        #pragma unroll
        for (int q = 0; q < 8; q++) {
            int n = q * 8 + tig * 2;
            if (d0 >= 0) {
                atomicAdd(p0 + n,     acc[mt][q][0]);
                atomicAdd(p0 + n + 1, acc[mt][q][1]);
            }
            if (d1 >= 0) {
                atomicAdd(p1 + n,     acc[mt][q][2]);
                atomicAdd(p1 + n + 1, acc[mt][q][3]);
            }
        }
    }
}

// ---------------- relu out (one float4 per thread, PDL wait) ----------------
__global__ void __launch_bounds__(256)
relu_out_kernel(const float4* __restrict__ in, float4* __restrict__ out, int n4)
{
    GDC_WAIT();
    int i = blockIdx.x * blockDim.x + threadIdx.x;
    if (i < n4) {
        float4 v = in[i];
        v.x = fmaxf(v.x, 0.0f); v.y = fmaxf(v.y, 0.0f);
        v.z = fmaxf(v.z, 0.0f); v.w = fmaxf(v.w, 0.0f);
        out[i] = v;
    }
}

// ---------------- launch -----------------------------------------------------
extern "C" void kernel_launch(void* const* d_in, const int* in_sizes, int n_in,
                              void* d_out, int out_size)
{
    const float* x      = (const float*)d_in[0];
    const int*   ei     = (const int*)  d_in[1];
    const float* ea     = (const float*)d_in[2];
    const float* w1_0   = (const float*)d_in[3];
    const float* b1_0   = (const float*)d_in[4];
    const float* w2_0   = (const float*)d_in[5];
    const float* b2_0   = (const float*)d_in[6];
    const float* root_0 = (const float*)d_in[7];
    const float* bias_0 = (const float*)d_in[8];
    const float* w1_1   = (const float*)d_in[9];
    const float* b1_1   = (const float*)d_in[10];
    const float* w2_1   = (const float*)d_in[11];
    const float* b2_1   = (const float*)d_in[12];
    const float* root_1 = (const float*)d_in[13];
    const float* bias_1 = (const float*)d_in[14];

    const int N = in_sizes[0] / 32;   // 20000
    const int E = in_sizes[1] / 2;    // 50000

    void* p;
    cudaGetSymbolAddress(&p, g_ht0);   __half* ht0 = (__half*)p;
    cudaGetSymbolAddress(&p, g_ht1);   __half* ht1 = (__half*)p;
    cudaGetSymbolAddress(&p, g_w2bh0); uint32_t* w2b0 = (uint32_t*)p;
    cudaGetSymbolAddress(&p, g_w2bh1); uint32_t* w2b1 = (uint32_t*)p;
    cudaGetSymbolAddress(&p, g_agg0);  float* agg0 = (float*)p;
    cudaGetSymbolAddress(&p, g_agg1);  float* agg1 = (float*)p;

    const int smem0 = 27648 + 128 * 36 * 4 + 512;   // 46592
    const int smem1 = 27648 + 128 * 68 * 4 + 512;   // 62976
    cudaFuncSetAttribute(fused_mma_kernel<32, false>,
                         cudaFuncAttributeMaxDynamicSharedMemorySize, smem0);
    cudaFuncSetAttribute(fused_mma_kernel<64, true>,
                         cudaFuncAttributeMaxDynamicSharedMemorySize, smem1);

    // ---- launch A: setup mega-kernel (plain launch) ----
    const int ebpj    = (E + 255) / 256;
    const int nb_mlp  = ebpj * H64;
    const int nb_prep = (66 * 2048) / 256;          // 528
    const int nb_root = (N * H64 + 255) / 256;
    setup_kernel<<<nb_mlp + nb_prep + nb_root, 256>>>(
        ea, w1_0, b1_0, w1_1, b1_1, w2_0, b2_0, w2_1, b2_1,
        x, root_0, bias_0, E, N, ebpj, nb_mlp, nb_prep);

    const int grid_fuse = (E + 127) / 128;
    const int ROOT_BLKS = 592;

    cudaLaunchAttribute pdl[1];
    pdl[0].id = cudaLaunchAttributeProgrammaticStreamSerialization;
    pdl[0].val.programmaticStreamSerializationAllowed = 1;

    // ---- launch B: fused layer 0 (PDL after setup) ----
    {
        cudaLaunchConfig_t cfg{};
        cfg.gridDim = dim3(grid_fuse);
        cfg.blockDim = dim3(128);
        cfg.dynamicSmemBytes = smem0;
        cfg.stream = 0;
        cfg.attrs = pdl;
        cfg.numAttrs = 1;
        const float* nW = nullptr; const float* nB = nullptr;
        cudaLaunchKernelEx(&cfg, fused_mma_kernel<32, false>,
                           x, ei, E, (const __half*)ht0, (const uint32_t*)w2b0,
                           agg0, nW, nB, N, grid_fuse, 0);
    }

    // ---- launch C: fused layer 1 + root1 backfill (PDL after B) ----
    {
        cudaLaunchConfig_t cfg{};
        cfg.gridDim = dim3(grid_fuse + ROOT_BLKS);
        cfg.blockDim = dim3(128);
        cfg.dynamicSmemBytes = smem1;
        cfg.stream = 0;
        cfg.attrs = pdl;
        cfg.numAttrs = 1;
        cudaLaunchKernelEx(&cfg, fused_mma_kernel<64, true>,
                           (const float*)agg0, ei, E, (const __half*)ht1,
                           (const uint32_t*)w2b1, agg1,
                           root_1, bias_1, N, grid_fuse, ROOT_BLKS);
    }

    // ---- launch D: relu out (PDL after C, one element per thread) ----
    {
        const int n4 = (N * H64) / 4;                // 320000
        cudaLaunchConfig_t cfg{};
        cfg.gridDim = dim3((n4 + 255) / 256);        // 1250
        cfg.blockDim = dim3(256);
        cfg.dynamicSmemBytes = 0;
        cfg.stream = 0;
        cfg.attrs = pdl;
        cfg.numAttrs = 1;
        cudaLaunchKernelEx(&cfg, relu_out_kernel,
                           (const float4*)agg1, (float4*)d_out, n4);
    }
}

// round 13
// speedup vs baseline: 1.1825x; 1.0553x over previous
#include <cuda_runtime.h>
#include <cuda_fp16.h>
#include <cstdint>

#define H64 64
#define EE_MAX 50000
#define NN_MAX 20000

// ---------------- scratch (static device globals) ---------------------------
__device__ uint32_t g_w2bh0[33 * 2176];         // fp16x2 packed B chunk64s, L0
__device__ uint32_t g_w2bh1[66 * 2176];         // fp16x2 packed B chunk64s, L1
__device__ float    g_agg0[NN_MAX * H64];
__device__ float    g_agg1[NN_MAX * H64];

// ---------------- PTX helpers ------------------------------------------------
__device__ __forceinline__ uint32_t smem_u32(const void* p) {
    return (uint32_t)__cvta_generic_to_shared(p);
}
__device__ __forceinline__ void cp_async16(uint32_t s, const void* g) {
    asm volatile("cp.async.cg.shared.global [%0], [%1], 16;" :: "r"(s), "l"(g));
}
#define CP_COMMIT() asm volatile("cp.async.commit_group;" ::: "memory")
#define CP_WAIT1()  asm volatile("cp.async.wait_group 1;" ::: "memory")
#define GDC_WAIT()  asm volatile("griddepcontrol.wait;" ::: "memory")

__device__ __forceinline__ uint32_t packf16(float v0, float v1) {
    uint32_t d;
    asm("cvt.rn.f16x2.f32 %0, %1, %2;" : "=r"(d) : "f"(v1), "f"(v0));
    return d;
}

// fp32-accumulator fp16 MMA (proven fastest path on sm_103 legacy tensor)
__device__ __forceinline__ void mma_f16(float* d, uint32_t a0, uint32_t a1,
                                        uint32_t a2, uint32_t a3,
                                        uint32_t b0, uint32_t b1) {
    asm volatile(
        "mma.sync.aligned.m16n8k16.row.col.f32.f16.f16.f32 "
        "{%0,%1,%2,%3}, {%4,%5,%6,%7}, {%8,%9}, {%0,%1,%2,%3};"
        : "+f"(d[0]), "+f"(d[1]), "+f"(d[2]), "+f"(d[3])
        : "r"(a0), "r"(a1), "r"(a2), "r"(a3), "r"(b0), "r"(b1));
}

// ---------------- kernel A: setup (B-pack + root0) --------------------------
__global__ void __launch_bounds__(256)
setup_kernel(const float* __restrict__ w2_0, const float* __restrict__ b2_0,
             const float* __restrict__ w2_1, const float* __restrict__ b2_1,
             const float* __restrict__ x,
             const float* __restrict__ root_0, const float* __restrict__ bias_0,
             int N, int nb_prep)
{
    int b = blockIdx.x, tid = threadIdx.x;

    if (b < nb_prep) {
        // ---- pack B chunk64 tables (pair layout) ----
        int idx = b * 256 + tid;                     // < 66*2048
        int c = idx >> 11, rem = idx & 2047;
        int row = rem >> 7;
        int n   = (rem >> 1) & 63;
        int p   = rem & 1;
        int s = row >> 2, t = row & 3;
        int k0 = 2 * t + 8 * p;
        int word = row * 136 + n * 2 + p;

        if (c < 33) {       // layer 0
            float v0 = 0.f, v1 = 0.f;
            if (c < 32) {
                int k = 2 * c + (s >> 1);
                int i = (s & 1) * 16 + k0;
                v0 = w2_0[k * 2048 + i * H64 + n];
                v1 = w2_0[k * 2048 + (i + 1) * H64 + n];
            } else if (s < 2) {
                int i = s * 16 + k0;
                v0 = b2_0[i * H64 + n];
                v1 = b2_0[(i + 1) * H64 + n];
            }
            g_w2bh0[c * 2176 + word] = packf16(v0, v1);
        }
        {                   // layer 1
            int ih = (c >= 33) ? 1 : 0;
            int cc = c - 33 * ih;
            float v0 = 0.f, v1 = 0.f;
            if (cc < 32) {
                int k = 2 * cc + (s >> 1);
                int i = ih * 32 + (s & 1) * 16 + k0;
                v0 = w2_1[k * 4096 + i * H64 + n];
                v1 = w2_1[k * 4096 + (i + 1) * H64 + n];
            } else if (s < 2) {
                int i = ih * 32 + s * 16 + k0;
                v0 = b2_1[i * H64 + n];
                v1 = b2_1[(i + 1) * H64 + n];
            }
            g_w2bh1[c * 2176 + word] = packf16(v0, v1);
        }
        return;
    }
    // ---- root0: agg0 = x @ root_0 + bias_0 ; agg1 = 0 ----
    int idx = (b - nb_prep) * 256 + tid;
    if (idx >= N * H64) return;
    int n = idx >> 6, t = idx & 63;
    float v = __ldg(&bias_0[t]);
    const float* xr = x + (size_t)n * 32;
    #pragma unroll
    for (int i = 0; i < 32; i++)
        v = fmaf(__ldg(&xr[i]), __ldg(&root_0[i * H64 + t]), v);
    g_agg0[idx] = v;
    g_agg1[idx] = 0.0f;
}

// ---------------- fused msg GEMM (mma.sync fp16->fp32) + scatter [+ root] ---
// blocks [0, gridFuse): CTA = 128 edges x 64 outs, 4 warps (32x64 warp tile),
//   K-chunks of 64, triple-buffered cp.async for B.
//   h computed IN-KERNEL from ea (2 scalars/edge) + w1/b1 in smem — no
//   materialized h tables at all.
// blocks >= gridFuse (layer 1 only): root1 term, grid-stride atomicAdd.
template<int IN_C, bool RELU_IN>
__global__ void __launch_bounds__(128, 3)
fused_mma_kernel(const float* __restrict__ x, const int* __restrict__ ei, int E,
                 const float* __restrict__ ea,
                 const float* __restrict__ w1, const float* __restrict__ b1,
                 const uint32_t* __restrict__ w2b,
                 float* __restrict__ agg,
                 const float* __restrict__ rootW, const float* __restrict__ rootB,
                 int N, int gridFuse, int rootBlocks)
{
    constexpr int NCHUNK = (IN_C == 32) ? 33 : 66;
    constexpr int XROW   = IN_C + 4;
    constexpr int B_OFF  = 0;                 // 3 x 8704 = 26112
    constexpr int W1_OFF = 26112;             // 192 floats: w1row0|w1row1|b1
    constexpr int X_OFF  = 26880;
    constexpr int DST_OFF = X_OFF + 128 * XROW * 4;

    int tid = threadIdx.x;

    if (blockIdx.x >= (unsigned)gridFuse) {
        // ---- root backfill path (layer 1 only; no smem, no syncs) ----
        GDC_WAIT();
        int stride = rootBlocks * 128;
        for (int idx = (blockIdx.x - gridFuse) * 128 + tid; idx < N * H64; idx += stride) {
            int n = idx >> 6, t = idx & 63;
            float v = __ldg(&rootB[t]);
            const float* xr = x + (size_t)n * H64;
            #pragma unroll
            for (int i = 0; i < H64; i++)
                v = fmaf(fmaxf(__ldg(&xr[i]), 0.0f), __ldg(&rootW[i * H64 + t]), v);
            atomicAdd(&agg[idx], v);
        }
        return;
    }

    extern __shared__ char smem[];
    float* w1_s  = (float*)(smem + W1_OFF);
    float* x_s   = (float*)(smem + X_OFF);
    int*   dst_s = (int*)(smem + DST_OFF);
    uint32_t sbase = smem_u32(smem);

    int e0 = blockIdx.x * 128;

    const int w    = tid >> 5;
    const int lane = tid & 31;
    const int gid  = lane >> 2;
    const int tig  = lane & 3;

    int rows[4];
    #pragma unroll
    for (int j = 0; j < 4; j++) rows[j] = w * 32 + j * 8 + gid;

    // ---- prefetch B chunk (8704 B) ----
    auto prefetch = [&](int c) {
        if (c < NCHUNK) {
            int slot = c % 3;
            uint32_t bs = sbase + B_OFF + slot * 8704;
            const char* g = (const char*)w2b + (size_t)c * 8704;
            #pragma unroll
            for (int o = 0; o < 8192; o += 2048)
                cp_async16(bs + o + tid * 16, g + o + tid * 16);
            if (tid < 32) cp_async16(bs + 8192 + tid * 16, g + 8192 + tid * 16);
        }
        CP_COMMIT();
    };

    // ---- gather x[src] tile (relu on read for layer 1) ----
    auto gather_x = [&]() {
        constexpr int XV = IN_C / 4;
        for (int q = tid; q < 128 * XV; q += 128) {
            int e = q / XV, cc = q % XV;
            int ge = e0 + e;
            int s = (ge < E) ? ei[ge] : 0;
            float4 v = *(const float4*)(x + (size_t)s * IN_C + cc * 4);
            if (RELU_IN) {
                v.x = fmaxf(v.x, 0.0f); v.y = fmaxf(v.y, 0.0f);
                v.z = fmaxf(v.z, 0.0f); v.w = fmaxf(v.w, 0.0f);
            }
            *(float4*)&x_s[e * XROW + cc * 4] = v;
        }
    };

    // ---- pre-wait loads (harness inputs only): dst, ea, w1/b1 ----
    dst_s[tid] = (e0 + tid < E) ? ei[E + e0 + tid] : -1;
    float ea0r[4], ea1r[4];
    #pragma unroll
    for (int j = 0; j < 4; j++) {
        int ge = e0 + rows[j];
        bool ok = (ge < E);
        ea0r[j] = ok ? __ldg(&ea[2 * ge])     : 0.0f;
        ea1r[j] = ok ? __ldg(&ea[2 * ge + 1]) : 0.0f;
    }
    if (tid < 64) {
        w1_s[tid]       = __ldg(&w1[tid]);
        w1_s[64 + tid]  = __ldg(&w1[64 + tid]);
        w1_s[128 + tid] = __ldg(&b1[tid]);
    }

    if (RELU_IN) {
        // B tables written two kernels ago -> prefetch before the wait;
        // x == agg0 from the previous kernel -> gather after the wait.
        prefetch(0); prefetch(1);
        GDC_WAIT();
        gather_x();
    } else {
        // x is a harness input -> gather before the wait; tables need setup.
        gather_x();
        GDC_WAIT();
        prefetch(0); prefetch(1);
    }
    __syncthreads();   // x_s / dst_s / w1_s visible

    float xreg[4][8];
    auto load_xreg = [&](int ih) {
        #pragma unroll
        for (int r = 0; r < 4; r++)
            #pragma unroll
            for (int j = 0; j < 8; j++)
                xreg[r][j] = x_s[rows[r] * XROW + ih +
                                 (j >> 2) * 16 + 2 * tig + 8 * ((j >> 1) & 1) + (j & 1)];
    };
    load_xreg(0);

    float acc[2][8][4];
    #pragma unroll
    for (int mt = 0; mt < 2; mt++)
        #pragma unroll
        for (int q = 0; q < 8; q++)
            #pragma unroll
            for (int u = 0; u < 4; u++) acc[mt][q][u] = 0.0f;

    for (int c = 0; c < NCHUNK; c++) {
        if (IN_C == 64 && c == 33) load_xreg(32);
        CP_WAIT1();
        __syncthreads();
        prefetch(c + 2);

        int slot = c % 3;
        bool isBias = (IN_C == 32) ? (c == 32) : (c == 32 || c == 65);
        int  cc = (IN_C == 32) ? c : ((c < 33) ? c : c - 33);
        float hk[2][4];
        if (isBias) {
            #pragma unroll
            for (int j = 0; j < 4; j++) { hk[0][j] = 1.0f; hk[1][j] = 1.0f; }
        } else {
            #pragma unroll
            for (int kk = 0; kk < 2; kk++) {
                int k = 2 * cc + kk;
                float wa = w1_s[k], wb = w1_s[64 + k], bb = w1_s[128 + k];
                #pragma unroll
                for (int j = 0; j < 4; j++)
                    hk[kk][j] = fmaxf(fmaf(ea0r[j], wa, fmaf(ea1r[j], wb, bb)), 0.0f);
            }
        }

        uint32_t bbase = sbase + B_OFF + slot * 8704;
        #pragma unroll
        for (int s = 0; s < 4; s++) {
            int kk = s >> 1, jb = (s & 1) * 4;
            uint32_t a[2][4];
            #pragma unroll
            for (int mt = 0; mt < 2; mt++) {
                float h0 = hk[kk][mt * 2], h1 = hk[kk][mt * 2 + 1];
                const float* x0 = xreg[mt * 2];
                const float* x1 = xreg[mt * 2 + 1];
                a[mt][0] = packf16(h0 * x0[jb + 0], h0 * x0[jb + 1]);
                a[mt][1] = packf16(h1 * x1[jb + 0], h1 * x1[jb + 1]);
                a[mt][2] = packf16(h0 * x0[jb + 2], h0 * x0[jb + 3]);
                a[mt][3] = packf16(h1 * x1[jb + 2], h1 * x1[jb + 3]);
            }
            uint32_t brow = bbase + (uint32_t)(s * 4 + tig) * 544 + (uint32_t)gid * 8;
            #pragma unroll
            for (int q = 0; q < 8; q++) {
                uint32_t b0, b1r;
                asm volatile("ld.shared.v2.b32 {%0, %1}, [%2];"
                             : "=r"(b0), "=r"(b1r) : "r"(brow + q * 64));
                mma_f16(acc[0][q], a[0][0], a[0][1], a[0][2], a[0][3], b0, b1r);
                mma_f16(acc[1][q], a[1][0], a[1][1], a[1][2], a[1][3], b0, b1r);
            }
        }
    }

    // ---- scatter-add into agg[dst] ----
    #pragma unroll
    for (int mt = 0; mt < 2; mt++) {
        int d0 = dst_s[rows[mt * 2]];
        int d1 = dst_s[rows[mt * 2 + 1]];
        float* p0 = agg + (size_t)(d0 < 0 ? 0 : d0) * H64;
        float* p1 = agg + (size_t)(d1 < 0 ? 0 : d1) * H64;
        #pragma unroll
        for (int q = 0; q < 8; q++) {
            int n = q * 8 + tig * 2;
            if (d0 >= 0) {
                atomicAdd(p0 + n,     acc[mt][q][0]);
                atomicAdd(p0 + n + 1, acc[mt][q][1]);
            }
            if (d1 >= 0) {
                atomicAdd(p1 + n,     acc[mt][q][2]);
                atomicAdd(p1 + n + 1, acc[mt][q][3]);
            }
        }
    }
}

// ---------------- relu out (one float4 per thread, PDL wait) ----------------
__global__ void __launch_bounds__(256)
relu_out_kernel(const float4* __restrict__ in, float4* __restrict__ out, int n4)
{
    GDC_WAIT();
    int i = blockIdx.x * blockDim.x + threadIdx.x;
    if (i < n4) {
        float4 v = in[i];
        v.x = fmaxf(v.x, 0.0f); v.y = fmaxf(v.y, 0.0f);
        v.z = fmaxf(v.z, 0.0f); v.w = fmaxf(v.w, 0.0f);
        out[i] = v;
    }
}

// ---------------- launch -----------------------------------------------------
extern "C" void kernel_launch(void* const* d_in, const int* in_sizes, int n_in,
                              void* d_out, int out_size)
{
    const float* x      = (const float*)d_in[0];
    const int*   ei     = (const int*)  d_in[1];
    const float* ea     = (const float*)d_in[2];
    const float* w1_0   = (const float*)d_in[3];
    const float* b1_0   = (const float*)d_in[4];
    const float* w2_0   = (const float*)d_in[5];
    const float* b2_0   = (const float*)d_in[6];
    const float* root_0 = (const float*)d_in[7];
    const float* bias_0 = (const float*)d_in[8];
    const float* w1_1   = (const float*)d_in[9];
    const float* b1_1   = (const float*)d_in[10];
    const float* w2_1   = (const float*)d_in[11];
    const float* b2_1   = (const float*)d_in[12];
    const float* root_1 = (const float*)d_in[13];
    const float* bias_1 = (const float*)d_in[14];

    const int N = in_sizes[0] / 32;   // 20000
    const int E = in_sizes[1] / 2;    // 50000

    void* p;
    cudaGetSymbolAddress(&p, g_w2bh0); uint32_t* w2b0 = (uint32_t*)p;
    cudaGetSymbolAddress(&p, g_w2bh1); uint32_t* w2b1 = (uint32_t*)p;
    cudaGetSymbolAddress(&p, g_agg0);  float* agg0 = (float*)p;
    cudaGetSymbolAddress(&p, g_agg1);  float* agg1 = (float*)p;

    const int smem0 = 26880 + 128 * 36 * 4 + 512;   // 45824
    const int smem1 = 26880 + 128 * 68 * 4 + 512;   // 62208
    cudaFuncSetAttribute(fused_mma_kernel<32, false>,
                         cudaFuncAttributeMaxDynamicSharedMemorySize, smem0);
    cudaFuncSetAttribute(fused_mma_kernel<64, true>,
                         cudaFuncAttributeMaxDynamicSharedMemorySize, smem1);

    // ---- launch A: setup (B-pack + root0; edge MLP is now in-kernel) ----
    const int nb_prep = (66 * 2048) / 256;          // 528
    const int nb_root = (N * H64 + 255) / 256;      // 5000
    setup_kernel<<<nb_prep + nb_root, 256>>>(
        w2_0, b2_0, w2_1, b2_1, x, root_0, bias_0, N, nb_prep);

    const int grid_fuse = (E + 127) / 128;
    const int ROOT_BLKS = 592;

    cudaLaunchAttribute pdl[1];
    pdl[0].id = cudaLaunchAttributeProgrammaticStreamSerialization;
    pdl[0].val.programmaticStreamSerializationAllowed = 1;

    // ---- launch B: fused layer 0 (PDL after setup) ----
    {
        cudaLaunchConfig_t cfg{};
        cfg.gridDim = dim3(grid_fuse);
        cfg.blockDim = dim3(128);
        cfg.dynamicSmemBytes = smem0;
        cfg.stream = 0;
        cfg.attrs = pdl;
        cfg.numAttrs = 1;
        const float* nW = nullptr; const float* nB = nullptr;
        cudaLaunchKernelEx(&cfg, fused_mma_kernel<32, false>,
                           x, ei, E, ea, w1_0, b1_0, (const uint32_t*)w2b0,
                           agg0, nW, nB, N, grid_fuse, 0);
    }

    // ---- launch C: fused layer 1 + root1 backfill (PDL after B) ----
    {
        cudaLaunchConfig_t cfg{};
        cfg.gridDim = dim3(grid_fuse + ROOT_BLKS);
        cfg.blockDim = dim3(128);
        cfg.dynamicSmemBytes = smem1;
        cfg.stream = 0;
        cfg.attrs = pdl;
        cfg.numAttrs = 1;
        cudaLaunchKernelEx(&cfg, fused_mma_kernel<64, true>,
                           (const float*)agg0, ei, E, ea, w1_1, b1_1,
                           (const uint32_t*)w2b1, agg1,
                           root_1, bias_1, N, grid_fuse, ROOT_BLKS);
    }

    // ---- launch D: relu out (PDL after C, one element per thread) ----
    {
        const int n4 = (N * H64) / 4;                // 320000
        cudaLaunchConfig_t cfg{};
        cfg.gridDim = dim3((n4 + 255) / 256);        // 1250
        cfg.blockDim = dim3(256);
        cfg.dynamicSmemBytes = 0;
        cfg.stream = 0;
        cfg.attrs = pdl;
        cfg.numAttrs = 1;
        cudaLaunchKernelEx(&cfg, relu_out_kernel,
                           (const float4*)agg1, (float4*)d_out, n4);
    }
}

// round 14
// speedup vs baseline: 1.2418x; 1.0502x over previous
#include <cuda_runtime.h>
#include <cuda_fp16.h>
#include <cstdint>

#define H64 64
#define EE_MAX 50000
#define NN_MAX 20000

// ---------------- scratch (static device globals) ---------------------------
__device__ uint32_t g_w2bh0[33 * 2176];         // fp16x2 packed B chunk64s, L0
__device__ uint32_t g_w2bh1[66 * 2176];         // fp16x2 packed B chunk64s, L1
__device__ float    g_agg0[NN_MAX * H64];
__device__ float    g_agg1[NN_MAX * H64];

// ---------------- PTX helpers ------------------------------------------------
__device__ __forceinline__ uint32_t smem_u32(const void* p) {
    return (uint32_t)__cvta_generic_to_shared(p);
}
__device__ __forceinline__ void cp_async16(uint32_t s, const void* g) {
    asm volatile("cp.async.cg.shared.global [%0], [%1], 16;" :: "r"(s), "l"(g));
}
#define CP_COMMIT() asm volatile("cp.async.commit_group;" ::: "memory")
#define CP_WAIT1()  asm volatile("cp.async.wait_group 1;" ::: "memory")
#define GDC_WAIT()  asm volatile("griddepcontrol.wait;" ::: "memory")

__device__ __forceinline__ uint32_t packf16(float v0, float v1) {
    uint32_t d;
    asm("cvt.rn.f16x2.f32 %0, %1, %2;" : "=r"(d) : "f"(v1), "f"(v0));
    return d;
}

// fp32-accumulator fp16 MMA (proven fastest path on sm_103 legacy tensor)
__device__ __forceinline__ void mma_f16(float* d, uint32_t a0, uint32_t a1,
                                        uint32_t a2, uint32_t a3,
                                        uint32_t b0, uint32_t b1) {
    asm volatile(
        "mma.sync.aligned.m16n8k16.row.col.f32.f16.f16.f32 "
        "{%0,%1,%2,%3}, {%4,%5,%6,%7}, {%8,%9}, {%0,%1,%2,%3};"
        : "+f"(d[0]), "+f"(d[1]), "+f"(d[2]), "+f"(d[3])
        : "r"(a0), "r"(a1), "r"(a2), "r"(a3), "r"(b0), "r"(b1));
}

// ---------------- kernel A: setup (B-pack + zero both agg) ------------------
__global__ void __launch_bounds__(256)
setup_kernel(const float* __restrict__ w2_0, const float* __restrict__ b2_0,
             const float* __restrict__ w2_1, const float* __restrict__ b2_1,
             int N, int nb_prep)
{
    int b = blockIdx.x, tid = threadIdx.x;

    if (b < nb_prep) {
        // ---- pack B chunk64 tables (pair layout) ----
        int idx = b * 256 + tid;                     // < 66*2048
        int c = idx >> 11, rem = idx & 2047;
        int row = rem >> 7;
        int n   = (rem >> 1) & 63;
        int p   = rem & 1;
        int s = row >> 2, t = row & 3;
        int k0 = 2 * t + 8 * p;
        int word = row * 136 + n * 2 + p;

        if (c < 33) {       // layer 0
            float v0 = 0.f, v1 = 0.f;
            if (c < 32) {
                int k = 2 * c + (s >> 1);
                int i = (s & 1) * 16 + k0;
                v0 = w2_0[k * 2048 + i * H64 + n];
                v1 = w2_0[k * 2048 + (i + 1) * H64 + n];
            } else if (s < 2) {
                int i = s * 16 + k0;
                v0 = b2_0[i * H64 + n];
                v1 = b2_0[(i + 1) * H64 + n];
            }
            g_w2bh0[c * 2176 + word] = packf16(v0, v1);
        }
        {                   // layer 1
            int ih = (c >= 33) ? 1 : 0;
            int cc = c - 33 * ih;
            float v0 = 0.f, v1 = 0.f;
            if (cc < 32) {
                int k = 2 * cc + (s >> 1);
                int i = ih * 32 + (s & 1) * 16 + k0;
                v0 = w2_1[k * 4096 + i * H64 + n];
                v1 = w2_1[k * 4096 + (i + 1) * H64 + n];
            } else if (s < 2) {
                int i = ih * 32 + s * 16 + k0;
                v0 = b2_1[i * H64 + n];
                v1 = b2_1[(i + 1) * H64 + n];
            }
            g_w2bh1[c * 2176 + word] = packf16(v0, v1);
        }
        return;
    }
    // ---- zero both agg buffers (float4) ----
    int idx = (b - nb_prep) * 256 + tid;
    if (idx < (N * H64) / 4) {
        float4 z = make_float4(0.f, 0.f, 0.f, 0.f);
        ((float4*)g_agg0)[idx] = z;
        ((float4*)g_agg1)[idx] = z;
    }
}

// ---------------- fused msg GEMM (mma.sync fp16->fp32) + scatter [+ root] ---
// blocks [0, gridFuse): CTA = 128 edges x 64 outs, 4 warps (32x64 warp tile),
//   K-chunks of 64, triple-buffered cp.async for B; h computed in-kernel.
// blocks >= gridFuse: root term for this layer, grid-stride atomicAdd
//   (agg pre-zeroed in setup) — overlaps with the tensor work.
template<int IN_C, bool RELU_IN>
__global__ void __launch_bounds__(128, 3)
fused_mma_kernel(const float* __restrict__ x, const int* __restrict__ ei, int E,
                 const float* __restrict__ ea,
                 const float* __restrict__ w1, const float* __restrict__ b1,
                 const uint32_t* __restrict__ w2b,
                 float* __restrict__ agg,
                 const float* __restrict__ rootW, const float* __restrict__ rootB,
                 int N, int gridFuse, int rootBlocks)
{
    constexpr int NCHUNK = (IN_C == 32) ? 33 : 66;
    constexpr int XROW   = IN_C + 4;
    constexpr int B_OFF  = 0;                 // 3 x 8704 = 26112
    constexpr int W1_OFF = 26112;             // 192 floats: w1row0|w1row1|b1
    constexpr int X_OFF  = 26880;
    constexpr int DST_OFF = X_OFF + 128 * XROW * 4;

    int tid = threadIdx.x;

    if (blockIdx.x >= (unsigned)gridFuse) {
        // ---- root backfill path (no smem, no syncs) ----
        GDC_WAIT();
        int stride = rootBlocks * 128;
        for (int idx = (blockIdx.x - gridFuse) * 128 + tid; idx < N * H64; idx += stride) {
            int n = idx >> 6, t = idx & 63;
            float v = __ldg(&rootB[t]);
            const float* xr = x + (size_t)n * IN_C;
            #pragma unroll
            for (int i = 0; i < IN_C; i++) {
                float xv = __ldg(&xr[i]);
                if (RELU_IN) xv = fmaxf(xv, 0.0f);
                v = fmaf(xv, __ldg(&rootW[i * H64 + t]), v);
            }
            atomicAdd(&agg[idx], v);
        }
        return;
    }

    extern __shared__ char smem[];
    float* w1_s  = (float*)(smem + W1_OFF);
    float* x_s   = (float*)(smem + X_OFF);
    int*   dst_s = (int*)(smem + DST_OFF);
    uint32_t sbase = smem_u32(smem);

    int e0 = blockIdx.x * 128;

    const int w    = tid >> 5;
    const int lane = tid & 31;
    const int gid  = lane >> 2;
    const int tig  = lane & 3;

    int rows[4];
    #pragma unroll
    for (int j = 0; j < 4; j++) rows[j] = w * 32 + j * 8 + gid;

    // ---- prefetch B chunk (8704 B) ----
    auto prefetch = [&](int c) {
        if (c < NCHUNK) {
            int slot = c % 3;
            uint32_t bs = sbase + B_OFF + slot * 8704;
            const char* g = (const char*)w2b + (size_t)c * 8704;
            #pragma unroll
            for (int o = 0; o < 8192; o += 2048)
                cp_async16(bs + o + tid * 16, g + o + tid * 16);
            if (tid < 32) cp_async16(bs + 8192 + tid * 16, g + 8192 + tid * 16);
        }
        CP_COMMIT();
    };

    // ---- gather x[src] tile (relu on read for layer 1) ----
    auto gather_x = [&]() {
        constexpr int XV = IN_C / 4;
        for (int q = tid; q < 128 * XV; q += 128) {
            int e = q / XV, cc = q % XV;
            int ge = e0 + e;
            int s = (ge < E) ? ei[ge] : 0;
            float4 v = *(const float4*)(x + (size_t)s * IN_C + cc * 4);
            if (RELU_IN) {
                v.x = fmaxf(v.x, 0.0f); v.y = fmaxf(v.y, 0.0f);
                v.z = fmaxf(v.z, 0.0f); v.w = fmaxf(v.w, 0.0f);
            }
            *(float4*)&x_s[e * XROW + cc * 4] = v;
        }
    };

    // ---- pre-wait loads (harness inputs only): dst, ea, w1/b1 ----
    dst_s[tid] = (e0 + tid < E) ? ei[E + e0 + tid] : -1;
    float ea0r[4], ea1r[4];
    #pragma unroll
    for (int j = 0; j < 4; j++) {
        int ge = e0 + rows[j];
        bool ok = (ge < E);
        ea0r[j] = ok ? __ldg(&ea[2 * ge])     : 0.0f;
        ea1r[j] = ok ? __ldg(&ea[2 * ge + 1]) : 0.0f;
    }
    if (tid < 64) {
        w1_s[tid]       = __ldg(&w1[tid]);
        w1_s[64 + tid]  = __ldg(&w1[64 + tid]);
        w1_s[128 + tid] = __ldg(&b1[tid]);
    }

    if (RELU_IN) {
        // B tables written two kernels ago -> prefetch before the wait;
        // x == agg0 from the previous kernel -> gather after the wait.
        prefetch(0); prefetch(1);
        GDC_WAIT();
        gather_x();
    } else {
        // x is a harness input -> gather before the wait; tables need setup.
        gather_x();
        GDC_WAIT();
        prefetch(0); prefetch(1);
    }
    __syncthreads();   // x_s / dst_s / w1_s visible

    float xreg[4][8];
    auto load_xreg = [&](int ih) {
        #pragma unroll
        for (int r = 0; r < 4; r++)
            #pragma unroll
            for (int j = 0; j < 8; j++)
                xreg[r][j] = x_s[rows[r] * XROW + ih +
                                 (j >> 2) * 16 + 2 * tig + 8 * ((j >> 1) & 1) + (j & 1)];
    };
    load_xreg(0);

    float acc[2][8][4];
    #pragma unroll
    for (int mt = 0; mt < 2; mt++)
        #pragma unroll
        for (int q = 0; q < 8; q++)
            #pragma unroll
            for (int u = 0; u < 4; u++) acc[mt][q][u] = 0.0f;

    for (int c = 0; c < NCHUNK; c++) {
        if (IN_C == 64 && c == 33) load_xreg(32);
        CP_WAIT1();
        __syncthreads();
        prefetch(c + 2);

        int slot = c % 3;
        bool isBias = (IN_C == 32) ? (c == 32) : (c == 32 || c == 65);
        int  cc = (IN_C == 32) ? c : ((c < 33) ? c : c - 33);
        float hk[2][4];
        if (isBias) {
            #pragma unroll
            for (int j = 0; j < 4; j++) { hk[0][j] = 1.0f; hk[1][j] = 1.0f; }
        } else {
            #pragma unroll
            for (int kk = 0; kk < 2; kk++) {
                int k = 2 * cc + kk;
                float wa = w1_s[k], wb = w1_s[64 + k], bb = w1_s[128 + k];
                #pragma unroll
                for (int j = 0; j < 4; j++)
                    hk[kk][j] = fmaxf(fmaf(ea0r[j], wa, fmaf(ea1r[j], wb, bb)), 0.0f);
            }
        }

        uint32_t bbase = sbase + B_OFF + slot * 8704;
        #pragma unroll
        for (int s = 0; s < 4; s++) {
            int kk = s >> 1, jb = (s & 1) * 4;
            uint32_t a[2][4];
            #pragma unroll
            for (int mt = 0; mt < 2; mt++) {
                float h0 = hk[kk][mt * 2], h1 = hk[kk][mt * 2 + 1];
                const float* x0 = xreg[mt * 2];
                const float* x1 = xreg[mt * 2 + 1];
                a[mt][0] = packf16(h0 * x0[jb + 0], h0 * x0[jb + 1]);
                a[mt][1] = packf16(h1 * x1[jb + 0], h1 * x1[jb + 1]);
                a[mt][2] = packf16(h0 * x0[jb + 2], h0 * x0[jb + 3]);
                a[mt][3] = packf16(h1 * x1[jb + 2], h1 * x1[jb + 3]);
            }
            uint32_t brow = bbase + (uint32_t)(s * 4 + tig) * 544 + (uint32_t)gid * 8;
            #pragma unroll
            for (int q = 0; q < 8; q++) {
                uint32_t b0, b1r;
                asm volatile("ld.shared.v2.b32 {%0, %1}, [%2];"
                             : "=r"(b0), "=r"(b1r) : "r"(brow + q * 64));
                mma_f16(acc[0][q], a[0][0], a[0][1], a[0][2], a[0][3], b0, b1r);
                mma_f16(acc[1][q], a[1][0], a[1][1], a[1][2], a[1][3], b0, b1r);
            }
        }
    }

    // ---- scatter-add into agg[dst] ----
    #pragma unroll
    for (int mt = 0; mt < 2; mt++) {
        int d0 = dst_s[rows[mt * 2]];
        int d1 = dst_s[rows[mt * 2 + 1]];
        float* p0 = agg + (size_t)(d0 < 0 ? 0 : d0) * H64;
        float* p1 = agg + (size_t)(d1 < 0 ? 0 : d1) * H64;
        #pragma unroll
        for (int q = 0; q < 8; q++) {
            int n = q * 8 + tig * 2;
            if (d0 >= 0) {
                atomicAdd(p0 + n,     acc[mt][q][0]);
                atomicAdd(p0 + n + 1, acc[mt][q][1]);
            }
            if (d1 >= 0) {
                atomicAdd(p1 + n,     acc[mt][q][2]);
                atomicAdd(p1 + n + 1, acc[mt][q][3]);
            }
        }
    }
}

// ---------------- relu out (two independent float4 per thread, PDL wait) ----
__global__ void __launch_bounds__(256)
relu_out_kernel(const float4* __restrict__ in, float4* __restrict__ out, int half4)
{
    GDC_WAIT();
    int i = blockIdx.x * blockDim.x + threadIdx.x;
    if (i < half4) {
        float4 a = in[i];
        float4 b = in[i + half4];
        a.x = fmaxf(a.x, 0.0f); a.y = fmaxf(a.y, 0.0f);
        a.z = fmaxf(a.z, 0.0f); a.w = fmaxf(a.w, 0.0f);
        b.x = fmaxf(b.x, 0.0f); b.y = fmaxf(b.y, 0.0f);
        b.z = fmaxf(b.z, 0.0f); b.w = fmaxf(b.w, 0.0f);
        out[i] = a;
        out[i + half4] = b;
    }
}

// ---------------- launch -----------------------------------------------------
extern "C" void kernel_launch(void* const* d_in, const int* in_sizes, int n_in,
                              void* d_out, int out_size)
{
    const float* x      = (const float*)d_in[0];
    const int*   ei     = (const int*)  d_in[1];
    const float* ea     = (const float*)d_in[2];
    const float* w1_0   = (const float*)d_in[3];
    const float* b1_0   = (const float*)d_in[4];
    const float* w2_0   = (const float*)d_in[5];
    const float* b2_0   = (const float*)d_in[6];
    const float* root_0 = (const float*)d_in[7];
    const float* bias_0 = (const float*)d_in[8];
    const float* w1_1   = (const float*)d_in[9];
    const float* b1_1   = (const float*)d_in[10];
    const float* w2_1   = (const float*)d_in[11];
    const float* b2_1   = (const float*)d_in[12];
    const float* root_1 = (const float*)d_in[13];
    const float* bias_1 = (const float*)d_in[14];

    const int N = in_sizes[0] / 32;   // 20000
    const int E = in_sizes[1] / 2;    // 50000

    void* p;
    cudaGetSymbolAddress(&p, g_w2bh0); uint32_t* w2b0 = (uint32_t*)p;
    cudaGetSymbolAddress(&p, g_w2bh1); uint32_t* w2b1 = (uint32_t*)p;
    cudaGetSymbolAddress(&p, g_agg0);  float* agg0 = (float*)p;
    cudaGetSymbolAddress(&p, g_agg1);  float* agg1 = (float*)p;

    const int smem0 = 26880 + 128 * 36 * 4 + 512;   // 45824
    const int smem1 = 26880 + 128 * 68 * 4 + 512;   // 62208
    cudaFuncSetAttribute(fused_mma_kernel<32, false>,
                         cudaFuncAttributeMaxDynamicSharedMemorySize, smem0);
    cudaFuncSetAttribute(fused_mma_kernel<64, true>,
                         cudaFuncAttributeMaxDynamicSharedMemorySize, smem1);

    // ---- launch A: setup (B-pack + zero agg; root terms now backfill) ----
    const int nb_prep = (66 * 2048) / 256;          // 528
    const int nb_zero = (N * H64 / 4 + 255) / 256;  // 1250
    setup_kernel<<<nb_prep + nb_zero, 256>>>(
        w2_0, b2_0, w2_1, b2_1, N, nb_prep);

    const int grid_fuse = (E + 127) / 128;
    const int ROOT_BLKS = 592;

    cudaLaunchAttribute pdl[1];
    pdl[0].id = cudaLaunchAttributeProgrammaticStreamSerialization;
    pdl[0].val.programmaticStreamSerializationAllowed = 1;

    // ---- launch B: fused layer 0 + root0 backfill (PDL after setup) ----
    {
        cudaLaunchConfig_t cfg{};
        cfg.gridDim = dim3(grid_fuse + ROOT_BLKS);
        cfg.blockDim = dim3(128);
        cfg.dynamicSmemBytes = smem0;
        cfg.stream = 0;
        cfg.attrs = pdl;
        cfg.numAttrs = 1;
        cudaLaunchKernelEx(&cfg, fused_mma_kernel<32, false>,
                           x, ei, E, ea, w1_0, b1_0, (const uint32_t*)w2b0,
                           agg0, root_0, bias_0, N, grid_fuse, ROOT_BLKS);
    }

    // ---- launch C: fused layer 1 + root1 backfill (PDL after B) ----
    {
        cudaLaunchConfig_t cfg{};
        cfg.gridDim = dim3(grid_fuse + ROOT_BLKS);
        cfg.blockDim = dim3(128);
        cfg.dynamicSmemBytes = smem1;
        cfg.stream = 0;
        cfg.attrs = pdl;
        cfg.numAttrs = 1;
        cudaLaunchKernelEx(&cfg, fused_mma_kernel<64, true>,
                           (const float*)agg0, ei, E, ea, w1_1, b1_1,
                           (const uint32_t*)w2b1, agg1,
                           root_1, bias_1, N, grid_fuse, ROOT_BLKS);
    }

    // ---- launch D: relu out (PDL after C, 2 float4 per thread) ----
    {
        const int half4 = (N * H64) / 8;             // 160000
        cudaLaunchConfig_t cfg{};
        cfg.gridDim = dim3((half4 + 255) / 256);     // 625
        cfg.blockDim = dim3(256);
        cfg.dynamicSmemBytes = 0;
        cfg.stream = 0;
        cfg.attrs = pdl;
        cfg.numAttrs = 1;
        cudaLaunchKernelEx(&cfg, relu_out_kernel,
                           (const float4*)agg1, (float4*)d_out, half4);
    }
}